// round 1
// baseline (speedup 1.0000x reference)
#include <cuda_runtime.h>
#include <stdint.h>

// fine_data region: [N*8, 64] f32, then fine_ijk region: [N*8, 3] written as f32
// (int values < 1024, exactly representable).

__global__ void upsample_data_kernel(const float4* __restrict__ src,
                                     float4* __restrict__ dst,
                                     int n16 /* N * 16 */) {
    int idx = blockIdx.x * blockDim.x + threadIdx.x;
    if (idx >= n16) return;
    int chunk = idx & 15;          // which 16B chunk of the 64-float row
    long long cr = idx >> 4;       // coarse row
    float4 v = src[idx];           // src[cr*16 + chunk]
    float4* base = dst + cr * 128 + chunk;  // 8 fine rows * 16 chunks
#pragma unroll
    for (int j = 0; j < 8; j++) {
        base[j * 16] = v;
    }
}

__global__ void upsample_ijk_kernel(const int* __restrict__ ijk,
                                    float4* __restrict__ dst, // fine_ijk region, float4 view
                                    int n /* N coarse voxels */) {
    int cr = blockIdx.x * blockDim.x + threadIdx.x;
    if (cr >= n) return;
    int x2 = 2 * ijk[cr * 3 + 0];
    int y2 = 2 * ijk[cr * 3 + 1];
    int z2 = 2 * ijk[cr * 3 + 2];

    // 8 sub-voxels * 3 coords = 24 floats = 6 float4, base offset cr*24 floats = cr*6 float4
    float c[24];
#pragma unroll
    for (int j = 0; j < 8; j++) {
        c[j * 3 + 0] = (float)(x2 + ((j >> 2) & 1));
        c[j * 3 + 1] = (float)(y2 + ((j >> 1) & 1));
        c[j * 3 + 2] = (float)(z2 + (j & 1));
    }
    float4* out = dst + (long long)cr * 6;
#pragma unroll
    for (int q = 0; q < 6; q++) {
        out[q] = make_float4(c[q * 4 + 0], c[q * 4 + 1], c[q * 4 + 2], c[q * 4 + 3]);
    }
}

extern "C" void kernel_launch(void* const* d_in, const int* in_sizes, int n_in,
                              void* d_out, int out_size) {
    const float* coarse_data = (const float*)d_in[0];
    const int*   coarse_ijk  = (const int*)d_in[1];
    float* out = (float*)d_out;

    int n = in_sizes[0] / 64;              // number of coarse voxels
    long long data_elems = (long long)n * 8 * 64;  // fine_data element count

    // Region A: fine_data
    int n16 = n * 16;
    int threads = 256;
    int blocks = (n16 + threads - 1) / threads;
    upsample_data_kernel<<<blocks, threads>>>((const float4*)coarse_data,
                                              (float4*)out, n16);

    // Region B: fine_ijk (as floats), starts right after fine_data
    float4* ijk_out = (float4*)(out + data_elems);
    int blocks2 = (n + threads - 1) / threads;
    upsample_ijk_kernel<<<blocks2, threads>>>(coarse_ijk, ijk_out, n);
}

// round 2
// speedup vs baseline: 1.0388x; 1.0388x over previous
#include <cuda_runtime.h>
#include <stdint.h>

// Output layout: fine_data [N*8, 64] f32, then fine_ijk [N*8, 3] written as f32
// (coords < 1024, exactly representable in f32).
//
// Fused kernel: block of 256 threads covers 16 coarse rows.
//   - data: thread t -> row r = bid*16 + t/16, chunk = t%16 (one float4),
//           replicated to 8 fine rows (stride 64 floats).
//   - ijk:  threads 0..95 each write one float4 of the ijk region
//           (16 rows * 24 floats = 96 float4 per block).

__global__ void __launch_bounds__(256) upsample_fused_kernel(
    const float4* __restrict__ src,     // coarse_data as float4, N*16 elems
    const int* __restrict__ ijk,        // coarse_ijk, N*3 ints
    float4* __restrict__ dst_data,      // fine_data as float4
    float4* __restrict__ dst_ijk,       // fine_ijk region as float4
    int n /* N coarse voxels, multiple of 16 assumed; guarded anyway */)
{
    const int t   = threadIdx.x;
    const int bid = blockIdx.x;

    // ---------- data replication ----------
    {
        int idx = bid * 256 + t;                 // coarse float4 index
        if (idx < n * 16) {
            int chunk = idx & 15;
            long long cr = idx >> 4;
            float4 v = src[idx];
            float4* base = dst_data + cr * 128 + chunk; // 8 fine rows * 16 f4
#pragma unroll
            for (int j = 0; j < 8; j++) {
                base[j * 16] = v;
            }
        }
    }

    // ---------- ijk expansion ----------
    // Block covers coarse rows [bid*16, bid*16+16) -> 96 float4 of ijk output.
    if (t < 96) {
        long long q = (long long)bid * 96 + t;      // global float4 index in ijk region
        // Guard for tail (n not multiple of 16): total float4 = n*6
        if (q < (long long)n * 6) {
            long long e0 = q * 4;                   // first float element index
            float vals[4];
#pragma unroll
            for (int k = 0; k < 4; k++) {
                long long e = e0 + k;
                long long f = e / 3;                // fine voxel index
                int comp    = (int)(e - f * 3);     // 0,1,2
                long long cr = f >> 3;              // coarse row
                int sub      = (int)(f & 7);        // sub-voxel 0..7
                int c = ijk[cr * 3 + comp];
                int off = (sub >> (2 - comp)) & 1;  // meshgrid ij order
                vals[k] = (float)(2 * c + off);
            }
            dst_ijk[q] = make_float4(vals[0], vals[1], vals[2], vals[3]);
        }
    }
}

extern "C" void kernel_launch(void* const* d_in, const int* in_sizes, int n_in,
                              void* d_out, int out_size) {
    const float* coarse_data = (const float*)d_in[0];
    const int*   coarse_ijk  = (const int*)d_in[1];
    float* out = (float*)d_out;

    int n = in_sizes[0] / 64;                       // coarse voxel count
    long long data_elems = (long long)n * 8 * 64;   // fine_data float count

    float4* dst_data = (float4*)out;
    float4* dst_ijk  = (float4*)(out + data_elems);

    int blocks = (n + 15) / 16;                     // 16 coarse rows per block
    upsample_fused_kernel<<<blocks, 256>>>((const float4*)coarse_data,
                                           coarse_ijk, dst_data, dst_ijk, n);
}

// round 3
// speedup vs baseline: 1.0446x; 1.0056x over previous
#include <cuda_runtime.h>
#include <stdint.h>

// Output layout: fine_data [N*8, 64] f32, then fine_ijk [N*8, 3] written as f32
// (coords < 1024, exactly representable in f32).
//
// Fused kernel, 256 threads cover 16 coarse rows:
//   - ijk: threads 0..95 each emit one float4 of the ijk region (issued first
//          so the tiny ijk loads overlap the bulk stream).
//   - data: every thread loads one float4 of coarse_data (evict-first) and
//           stores it to the 8 fine rows (evict-first streaming stores).

__global__ void __launch_bounds__(256) upsample_fused_kernel(
    const float4* __restrict__ src,     // coarse_data as float4, N*16 elems
    const int* __restrict__ ijk,        // coarse_ijk, N*3 ints
    float4* __restrict__ dst_data,      // fine_data as float4
    float4* __restrict__ dst_ijk,       // fine_ijk region as float4
    int n)
{
    const int t   = threadIdx.x;
    const int bid = blockIdx.x;

    // ---------- data load issued first (longest latency) ----------
    int idx = bid * 256 + t;                 // coarse float4 index
    bool do_data = (idx < n * 16);
    float4 v;
    if (do_data) v = __ldcs(src + idx);

    // ---------- ijk expansion ----------
    if (t < 96) {
        long long q = (long long)bid * 96 + t;     // float4 index in ijk region
        if (q < (long long)n * 6) {
            long long e0 = q * 4;                  // first float element index
            float vals[4];
#pragma unroll
            for (int k = 0; k < 4; k++) {
                long long e = e0 + k;
                long long f = e / 3;               // fine voxel index
                int comp    = (int)(e - f * 3);    // 0,1,2
                long long cr = f >> 3;             // coarse row
                int sub      = (int)(f & 7);       // sub-voxel 0..7
                int c = __ldg(ijk + cr * 3 + comp);
                int off = (sub >> (2 - comp)) & 1; // meshgrid ij order
                vals[k] = (float)(2 * c + off);
            }
            __stcs(dst_ijk + q, make_float4(vals[0], vals[1], vals[2], vals[3]));
        }
    }

    // ---------- data replication (streaming stores) ----------
    if (do_data) {
        int chunk = idx & 15;
        long long cr = idx >> 4;
        float4* base = dst_data + cr * 128 + chunk; // 8 fine rows * 16 f4
#pragma unroll
        for (int j = 0; j < 8; j++) {
            __stcs(base + j * 16, v);
        }
    }
}

extern "C" void kernel_launch(void* const* d_in, const int* in_sizes, int n_in,
                              void* d_out, int out_size) {
    const float* coarse_data = (const float*)d_in[0];
    const int*   coarse_ijk  = (const int*)d_in[1];
    float* out = (float*)d_out;

    int n = in_sizes[0] / 64;                       // coarse voxel count
    long long data_elems = (long long)n * 8 * 64;   // fine_data float count

    float4* dst_data = (float4*)out;
    float4* dst_ijk  = (float4*)(out + data_elems);

    int blocks = (n + 15) / 16;                     // 16 coarse rows per block
    upsample_fused_kernel<<<blocks, 256>>>((const float4*)coarse_data,
                                           coarse_ijk, dst_data, dst_ijk, n);
}